// round 12
// baseline (speedup 1.0000x reference)
#include <cuda_runtime.h>
#include <cuda_fp16.h>
#include <cstdint>
#include <cstddef>

#define B_SZ   4
#define T_LEN  512
#define S_LEN  4096
#define HID    1024
#define NH     16
#define HD     64
#define NBH    (B_SZ * NH)

// ---------------------------------------------------------------------------
// helpers
// ---------------------------------------------------------------------------
__device__ __forceinline__ uint32_t smem_u32(const void* p) {
    uint32_t a;
    asm("{ .reg .u64 t; cvta.to.shared.u64 t, %1; cvt.u32.u64 %0, t; }" : "=r"(a) : "l"(p));
    return a;
}
// 64B-row tile swizzle (K-major [rows x 32] tiles)
__device__ __forceinline__ uint32_t swzoff(int row, int chunk) {
    const int v = (row & 3) ^ ((row >> 2) & 1);
    return (uint32_t)(row * 64 + (((chunk ^ v) & 3) << 4));
}
__device__ __forceinline__ void cpa16(uint32_t dst, const void* src) {
    asm volatile("cp.async.cg.shared.global [%0], [%1], 16;" :: "r"(dst), "l"(src));
}
#define CP_COMMIT() asm volatile("cp.async.commit_group;" ::: "memory")
#define CP_WAIT(n)  asm volatile("cp.async.wait_group %0;" :: "n"(n) : "memory")

__device__ __forceinline__ void ldsm4(uint32_t* r, uint32_t a) {
    asm volatile("ldmatrix.sync.aligned.m8n8.x4.shared.b16 {%0,%1,%2,%3}, [%4];"
                 : "=r"(r[0]), "=r"(r[1]), "=r"(r[2]), "=r"(r[3]) : "r"(a));
}
__device__ __forceinline__ void ldsm4t(uint32_t* r, uint32_t a) {
    asm volatile("ldmatrix.sync.aligned.m8n8.x4.trans.shared.b16 {%0,%1,%2,%3}, [%4];"
                 : "=r"(r[0]), "=r"(r[1]), "=r"(r[2]), "=r"(r[3]) : "r"(a));
}
__device__ __forceinline__ void mma_f16(float* d, const uint32_t* a, const uint32_t* b) {
    asm volatile("mma.sync.aligned.m16n8k16.row.col.f32.f16.f16.f32 "
                 "{%0,%1,%2,%3}, {%4,%5,%6,%7}, {%8,%9}, {%0,%1,%2,%3};"
                 : "+f"(d[0]), "+f"(d[1]), "+f"(d[2]), "+f"(d[3])
                 : "r"(a[0]), "r"(a[1]), "r"(a[2]), "r"(a[3]), "r"(b[0]), "r"(b[1]));
}
__device__ __forceinline__ void split2h(float v, __half& h, __half& l) {
    h = __float2half_rn(v);
    l = __float2half_rn(v - __half2float(h));
}
__device__ __forceinline__ uint32_t packh2(float a, float b) {
    __half2 h2;
    h2.x = __float2half_rn(a);
    h2.y = __float2half_rn(b);
    return *reinterpret_cast<uint32_t*>(&h2);
}

// Load a [ROWS x 32] fp16 tile (row stride = stride elems) into swizzled SMEM
template<int ROWS>
__device__ __forceinline__ void load_stage(uint32_t sbuf, const __half* g,
                                           int stride, int tid) {
    #pragma unroll
    for (int i = tid; i < ROWS * 4; i += 256) {
        const int row = i >> 2, ch = i & 3;
        cpa16(sbuf + swzoff(row, ch), g + (size_t)row * stride + ch * 8);
    }
}
// Load a [32 x 64] fp16 tile (128B rows, chunk-XOR swizzle) for trans-B (V)
__device__ __forceinline__ void load_vtile(uint32_t sbuf, const __half* g,
                                           int stride, int tid) {
    if (tid < 256) {
        const int row = tid >> 3, ch = tid & 7;
        cpa16(sbuf + (uint32_t)(row * 128 + (((ch ^ row) & 7) << 4)),
              g + (size_t)row * stride + ch * 8);
    }
}

// One 32-k stage, A single + B hi/lo, 2 products (Q/K projections).
__device__ __forceinline__ void stage_compute2(uint32_t sA,
                                               uint32_t sBh, uint32_t sBl,
                                               int wmr, int wnr, int lane,
                                               float (*acc)[4][4]) {
    const int l7 = lane & 7, l8 = (lane >> 3) & 1, l16 = (lane >> 4) & 1;
    const int arow = wmr + l7 + l8 * 8;
    const int brow = wnr + l16 * 8 + l7;
    #pragma unroll
    for (int ks = 0; ks < 2; ks++) {
        uint32_t ah[4][4], bh[2][4], bl[2][4];
        #pragma unroll
        for (int mi = 0; mi < 4; mi++)
            ldsm4(ah[mi], sA + swzoff(arow + mi * 16, ks * 2 + l16));
        #pragma unroll
        for (int p = 0; p < 2; p++) {
            const uint32_t off = swzoff(brow + p * 16, ks * 2 + l8);
            ldsm4(bh[p], sBh + off);
            ldsm4(bl[p], sBl + off);
        }
        #pragma unroll
        for (int mi = 0; mi < 4; mi++)
            #pragma unroll
            for (int nj = 0; nj < 4; nj++) {
                mma_f16(acc[mi][nj], ah[mi], &bh[nj >> 1][(nj & 1) * 2]);
                mma_f16(acc[mi][nj], ah[mi], &bl[nj >> 1][(nj & 1) * 2]);
            }
    }
}

// One 32-k stage, A single + B single, 1 product.
__device__ __forceinline__ void stage_compute1(uint32_t sA, uint32_t sB,
                                               int wmr, int wnr, int lane,
                                               float (*acc)[4][4]) {
    const int l7 = lane & 7, l8 = (lane >> 3) & 1, l16 = (lane >> 4) & 1;
    const int arow = wmr + l7 + l8 * 8;
    const int brow = wnr + l16 * 8 + l7;
    #pragma unroll
    for (int ks = 0; ks < 2; ks++) {
        uint32_t ah[4][4], bh[2][4];
        #pragma unroll
        for (int mi = 0; mi < 4; mi++)
            ldsm4(ah[mi], sA + swzoff(arow + mi * 16, ks * 2 + l16));
        #pragma unroll
        for (int p = 0; p < 2; p++)
            ldsm4(bh[p], sB + swzoff(brow + p * 16, ks * 2 + l8));
        #pragma unroll
        for (int mi = 0; mi < 4; mi++)
            #pragma unroll
            for (int nj = 0; nj < 4; nj++)
                mma_f16(acc[mi][nj], ah[mi], &bh[nj >> 1][(nj & 1) * 2]);
    }
}

// ---------------- scratch ----------------
__device__ __half g_qh[2048 * HID];
__device__ __half g_kh[16384 * HID];
__device__ __half g_vh[16384 * HID];
__device__ __half g_wqh[HID * HID], g_wql[HID * HID];
__device__ __half g_wkh[HID * HID], g_wkl[HID * HID];
__device__ __half g_wvh[HID * HID];
__device__ __half g_woh[HID * HID];
__device__ __half g_Qh[2048 * HID];
__device__ __half g_Kh[16384 * HID];
__device__ __half g_Vh[16384 * HID];
__device__ float  g_ps[(size_t)NBH * T_LEN * 32];   // partial row sums
__device__ float  g_rs[NBH * T_LEN];                // reciprocal row sums
__device__ __half g_ah[2048 * HID];

// ---------------- conversions ----------------
__global__ __launch_bounds__(256)
void conv_h(const float* __restrict__ X, __half* __restrict__ H) {
    const size_t u = (size_t)blockIdx.x * 256 + threadIdx.x;
    float2 v = reinterpret_cast<const float2*>(X)[u];
    reinterpret_cast<__half2*>(H)[u] =
        __halves2half2(__float2half_rn(v.x), __float2half_rn(v.y));
}
__global__ __launch_bounds__(256)
void conv_wT(const float* __restrict__ W, __half* __restrict__ WTh,
             __half* __restrict__ WTl) {
    __shared__ float t[32][33];
    const int k0 = blockIdx.x * 32, n0 = blockIdx.y * 32;
    const int tx = threadIdx.x, ty = threadIdx.y;
    for (int r = ty; r < 32; r += 8) t[r][tx] = W[(size_t)(k0 + r) * HID + n0 + tx];
    __syncthreads();
    for (int r = ty; r < 32; r += 8) {
        __half h, l;
        split2h(t[tx][r], h, l);
        WTh[(size_t)(n0 + r) * HID + k0 + tx] = h;
        if (WTl) WTl[(size_t)(n0 + r) * HID + k0 + tx] = l;
    }
}

// ---------------- Q/K projection (2-product weights, single fp16 out) ----------------
template<int MODE>  // 0: Q (*0.125)  1: K (+seg)
__global__ __launch_bounds__(256)
void proj2(const __half* __restrict__ A,
           const __half* __restrict__ Bh, const __half* __restrict__ Bl,
           const float* __restrict__ bias, const int* __restrict__ segids,
           const float* __restrict__ seg_emb, __half* __restrict__ outH) {
    extern __shared__ __align__(128) char sm[];
    const uint32_t sb = smem_u32(sm);
    const int tid = threadIdx.x, lane = tid & 31, w = tid >> 5;
    const int wmr = (w & 1) * 64, wnr = (w >> 1) * 32;
    const int n0 = blockIdx.x * 128, m0 = blockIdx.y * 128;
    const __half* gA  = A + (size_t)m0 * HID;
    const __half* gBh = Bh + (size_t)n0 * HID;
    const __half* gBl = Bl + (size_t)n0 * HID;

#define PJ_LOAD(st, ko) do {                                \
    const uint32_t b_ = sb + ((st) % 3) * 24576;            \
    load_stage<128>(b_ + 0,     gA  + (ko), HID, tid);      \
    load_stage<128>(b_ + 8192,  gBh + (ko), HID, tid);      \
    load_stage<128>(b_ + 16384, gBl + (ko), HID, tid);      \
    CP_COMMIT();                                            \
  } while (0)

    float acc[4][4][4] = {};
    PJ_LOAD(0, 0);
    PJ_LOAD(1, 32);
    const int NST = HID / 32;
    for (int s = 0; s < NST; s++) {
        if (s + 2 < NST) { PJ_LOAD(s + 2, (s + 2) * 32); CP_WAIT(2); }
        else if (s + 1 < NST) { CP_WAIT(1); }
        else { CP_WAIT(0); }
        __syncthreads();
        const uint32_t cur = sb + (s % 3) * 24576;
        stage_compute2(cur, cur + 8192, cur + 16384, wmr, wnr, lane, acc);
        __syncthreads();
    }
#undef PJ_LOAD

    const int mq = lane >> 2, nq = (lane & 3) * 2;
    #pragma unroll
    for (int mi = 0; mi < 4; mi++)
        #pragma unroll
        for (int half = 0; half < 2; half++) {
            const int m = m0 + wmr + mi * 16 + mq + half * 8;
            const int sid = (MODE == 1) ? segids[m] : 0;
            #pragma unroll
            for (int nj = 0; nj < 4; nj++) {
                const int n = n0 + wnr + nj * 8 + nq;
                float v0 = acc[mi][nj][half * 2 + 0] + bias[n];
                float v1 = acc[mi][nj][half * 2 + 1] + bias[n + 1];
                if (MODE == 1) {
                    v0 += seg_emb[(size_t)sid * HID + n];
                    v1 += seg_emb[(size_t)sid * HID + n + 1];
                }
                if (MODE == 0) { v0 *= 0.125f; v1 *= 0.125f; }
                *(__half2*)(outH + (size_t)m * HID + n) =
                    __halves2half2(__float2half_rn(v0), __float2half_rn(v1));
            }
        }
}

// ---------------- V/O projection (1-product) ----------------
template<int MODE>  // 0: V (fp16 out)  1: O (fp32 out)
__global__ __launch_bounds__(256)
void proj1(const __half* __restrict__ A, const __half* __restrict__ B,
           const float* __restrict__ bias, float* __restrict__ outF,
           __half* __restrict__ outH) {
    extern __shared__ __align__(128) char sm[];
    const uint32_t sb = smem_u32(sm);
    const int tid = threadIdx.x, lane = tid & 31, w = tid >> 5;
    const int wmr = (w & 1) * 64, wnr = (w >> 1) * 32;
    const int n0 = blockIdx.x * 128, m0 = blockIdx.y * 128;
    const __half* gA = A + (size_t)m0 * HID;
    const __half* gB = B + (size_t)n0 * HID;

#define P1_LOAD(st, ko) do {                                \
    const uint32_t b_ = sb + ((st) % 3) * 16384;            \
    load_stage<128>(b_ + 0,    gA + (ko), HID, tid);        \
    load_stage<128>(b_ + 8192, gB + (ko), HID, tid);        \
    CP_COMMIT();                                            \
  } while (0)

    float acc[4][4][4] = {};
    P1_LOAD(0, 0);
    P1_LOAD(1, 32);
    const int NST = HID / 32;
    for (int s = 0; s < NST; s++) {
        if (s + 2 < NST) { P1_LOAD(s + 2, (s + 2) * 32); CP_WAIT(2); }
        else if (s + 1 < NST) { CP_WAIT(1); }
        else { CP_WAIT(0); }
        __syncthreads();
        const uint32_t cur = sb + (s % 3) * 16384;
        stage_compute1(cur, cur + 8192, wmr, wnr, lane, acc);
        __syncthreads();
    }
#undef P1_LOAD

    const int mq = lane >> 2, nq = (lane & 3) * 2;
    #pragma unroll
    for (int mi = 0; mi < 4; mi++)
        #pragma unroll
        for (int half = 0; half < 2; half++) {
            const int m = m0 + wmr + mi * 16 + mq + half * 8;
            #pragma unroll
            for (int nj = 0; nj < 4; nj++) {
                const int n = n0 + wnr + nj * 8 + nq;
                float v0 = acc[mi][nj][half * 2 + 0] + bias[n];
                float v1 = acc[mi][nj][half * 2 + 1] + bias[n + 1];
                if (MODE == 0) {
                    *(__half2*)(outH + (size_t)m * HID + n) =
                        __halves2half2(__float2half_rn(v0), __float2half_rn(v1));
                } else {
                    *(float2*)(outF + (size_t)m * HID + n) = make_float2(v0, v1);
                }
            }
        }
}

// ---------------- rowsum pass: partial row sums of exp(QK^T - 4), no E store ----------------
__global__ __launch_bounds__(256)
void rowsum_pass(const __half* __restrict__ Qh, const __half* __restrict__ Kh,
                 const int* __restrict__ amask, float* __restrict__ gps) {
    extern __shared__ __align__(128) char sm[];
    __shared__ float psum[128][4];
    const uint32_t sb = smem_u32(sm);
    const int tid = threadIdx.x, lane = tid & 31, w = tid >> 5;
    const int wmr = (w & 1) * 64, wnr = (w >> 1) * 32;
    const int bh = blockIdx.z, b = bh >> 4, h = bh & 15;
    const int t0 = blockIdx.y * 128, s0 = blockIdx.x * 128;
    const __half* gA = Qh + (size_t)(b * T_LEN + t0) * HID + h * HD;
    const __half* gB = Kh + (size_t)(b * S_LEN + s0) * HID + h * HD;

    float acc[4][4][4] = {};
    load_stage<128>(sb + 0,    gA, HID, tid);
    load_stage<128>(sb + 8192, gB, HID, tid);
    CP_COMMIT();
    load_stage<128>(sb + 16384, gA + 32, HID, tid);
    load_stage<128>(sb + 24576, gB + 32, HID, tid);
    CP_COMMIT();
    for (int s = 0; s < 2; s++) {
        if (s == 0) CP_WAIT(1);
        else CP_WAIT(0);
        __syncthreads();
        const uint32_t cur = sb + s * 16384;
        stage_compute1(cur, cur + 8192, wmr, wnr, lane, acc);
        __syncthreads();
    }

    const int mq = lane >> 2, nq = (lane & 3) * 2;
    #pragma unroll
    for (int mi = 0; mi < 4; mi++)
        #pragma unroll
        for (int half = 0; half < 2; half++) {
            float rsum = 0.f;
            #pragma unroll
            for (int nj = 0; nj < 4; nj++) {
                const int sidx = s0 + wnr + nj * 8 + nq;
                if (amask[b * S_LEN + sidx] != 0)
                    rsum += __expf(acc[mi][nj][half * 2 + 0] - 4.f);
                if (amask[b * S_LEN + sidx + 1] != 0)
                    rsum += __expf(acc[mi][nj][half * 2 + 1] - 4.f);
            }
            rsum += __shfl_xor_sync(0xFFFFFFFFu, rsum, 1);
            rsum += __shfl_xor_sync(0xFFFFFFFFu, rsum, 2);
            if ((lane & 3) == 0)
                psum[wmr + mi * 16 + half * 8 + mq][w >> 1] = rsum;
        }
    __syncthreads();
    if (tid < 128) {
        const float tot = psum[tid][0] + psum[tid][1] + psum[tid][2] + psum[tid][3];
        gps[((size_t)bh * T_LEN + t0 + tid) * 32 + blockIdx.x] = tot;
    }
}

// ---------------- row-sum reduce -> reciprocal ----------------
__global__ __launch_bounds__(256)
void rowsum_reduce(const float* __restrict__ gps, float* __restrict__ rs) {
    const int r = blockIdx.x * 256 + threadIdx.x;
    const float4* p = reinterpret_cast<const float4*>(gps + (size_t)r * 32);
    float s = 0.f;
    #pragma unroll
    for (int i = 0; i < 8; i++) {
        float4 v = p[i];
        s += v.x + v.y + v.z + v.w;
    }
    rs[r] = 1.0f / s;
}

// ---------------- fused provenance: recompute scores, sum over heads ----------------
// grid (s-block=32, t-block=4, b=4); ring slot: Q0 Q1 K0 K1 rsrow = 33280 B, x2; mask @66560
// Depth-1 prefetch over the 2-slot ring (prefetch h+1 while computing h).
__global__ __launch_bounds__(256)
void prov_fused(const __half* __restrict__ Qh, const __half* __restrict__ Kh,
                const float* __restrict__ rs, const int* __restrict__ amask,
                float* __restrict__ out) {
    extern __shared__ __align__(128) char sm[];
    const uint32_t sb = smem_u32(sm);
    const int tid = threadIdx.x, lane = tid & 31, w = tid >> 5;
    const int wmr = (w & 1) * 64, wnr = (w >> 1) * 32;
    const int b = blockIdx.z, t0 = blockIdx.y * 128, s0 = blockIdx.x * 128;
    const int* mask_s = (const int*)(sm + 66560);

#define PR_LOAD(i, h) do {                                                       \
    const uint32_t b_ = sb + (i) * 33280;                                        \
    const __half* gQ_ = Qh + (size_t)(b * T_LEN + t0) * HID + (h) * HD;          \
    const __half* gK_ = Kh + (size_t)(b * S_LEN + s0) * HID + (h) * HD;          \
    load_stage<128>(b_ + 0,     gQ_,      HID, tid);                             \
    load_stage<128>(b_ + 8192,  gQ_ + 32, HID, tid);                             \
    load_stage<128>(b_ + 16384, gK_,      HID, tid);                             \
    load_stage<128>(b_ + 24576, gK_ + 32, HID, tid);                             \
    if (tid < 32) cpa16(b_ + 32768 + tid * 16,                                   \
                        rs + ((b * NH + (h)) * T_LEN + t0) + tid * 4);           \
    CP_COMMIT();                                                                 \
  } while (0)

    // mask for this s-block (joins ring-0's commit group)
    if (tid < 32) cpa16(sb + 66560 + tid * 16, amask + b * S_LEN + s0 + tid * 4);
    PR_LOAD(0, 0);

    const int mq = lane >> 2, nq = (lane & 3) * 2;
    float pacc[4][4][4] = {};
    for (int h = 0; h < NH; h++) {
        // Depth-1: prefetch h+1 into the OTHER slot, then wait for slot h.
        if (h + 1 < NH) { PR_LOAD((h + 1) & 1, h + 1); CP_WAIT(1); }
        else { CP_WAIT(0); }
        __syncthreads();
        const uint32_t cur = sb + (h & 1) * 33280;
        float sacc[4][4][4] = {};
        stage_compute1(cur, cur + 16384, wmr, wnr, lane, sacc);
        stage_compute1(cur + 8192, cur + 24576, wmr, wnr, lane, sacc);
        const float* rsrow = (const float*)(sm + (h & 1) * 33280 + 32768);
        #pragma unroll
        for (int mi = 0; mi < 4; mi++)
            #pragma unroll
            for (int half = 0; half < 2; half++) {
                const float inv = rsrow[wmr + mi * 16 + half * 8 + mq];
                #pragma unroll
                for (int nj = 0; nj < 4; nj++) {
                    const int sc = wnr + nj * 8 + nq;
                    if (mask_s[sc] != 0)
                        pacc[mi][nj][half * 2 + 0] +=
                            __expf(sacc[mi][nj][half * 2 + 0] - 4.f) * inv;
                    if (mask_s[sc + 1] != 0)
                        pacc[mi][nj][half * 2 + 1] +=
                            __expf(sacc[mi][nj][half * 2 + 1] - 4.f) * inv;
                }
            }
        __syncthreads();   // all reads of slot (h&1) done before next PR_LOAD reuses it
    }
#undef PR_LOAD

    #pragma unroll
    for (int mi = 0; mi < 4; mi++)
        #pragma unroll
        for (int half = 0; half < 2; half++) {
            const int t = t0 + wmr + mi * 16 + mq + half * 8;
            #pragma unroll
            for (int nj = 0; nj < 4; nj++) {
                const int s = s0 + wnr + nj * 8 + nq;
                *(float2*)(out + ((size_t)(b * T_LEN + t) << 12) + s) =
                    make_float2(pacc[mi][nj][half * 2 + 0] * (1.0f / NH),
                                pacc[mi][nj][half * 2 + 1] * (1.0f / NH));
            }
        }
}

// ---------------- fused PV (FA2-style): recompute S, exp, P.V, online rowsum ----------------
// grid (t-block=4, bh=64). smem: Q0 Q1 (16 KB) + ring[2]: K0 K1 V mask = 33280 B
__global__ __launch_bounds__(256)
void pv_fused(const __half* __restrict__ Qh, const __half* __restrict__ Kh,
              const __half* __restrict__ Vh, const int* __restrict__ amask,
              __half* __restrict__ attH) {
    extern __shared__ __align__(128) char sm[];
    const uint32_t sb = smem_u32(sm);
    const int tid = threadIdx.x, lane = tid & 31, w = tid >> 5;
    const int bh = blockIdx.y, b = bh >> 4, h = bh & 15;
    const int t0 = blockIdx.x * 128;
    const int l7 = lane & 7, l8 = (lane >> 3) & 1, l16 = (lane >> 4) & 1;
    const int g = lane >> 3, q = lane & 7;
    const __half* gQ = Qh + (size_t)(b * T_LEN + t0) * HID + h * HD;
    const __half* gK = Kh + (size_t)(b * S_LEN) * HID + h * HD;
    const __half* gV = Vh + (size_t)(b * S_LEN) * HID + h * HD;

#define PVF_LOAD(i, sblk) do {                                                    \
    const uint32_t b_ = sb + 16384 + (i) * 33280;                                 \
    load_stage<128>(b_ + 0,    gK + (size_t)(sblk) * 128 * HID,      HID, tid);   \
    load_stage<128>(b_ + 8192, gK + (size_t)(sblk) * 128 * HID + 32, HID, tid);   \
    load_vtile(b_ + 16384, gV + (size_t)((sblk) * 128 +  0) * HID, HID, tid);     \
    load_vtile(b_ + 20480, gV + (size_t)((sblk) * 128 + 32) * HID, HID, tid);     \
    load_vtile(b_ + 24576, gV + (size_t)((sblk) * 128 + 64) * HID, HID, tid);     \
    load_vtile(b_ + 28672, gV + (size_t)((sblk) * 128 + 96) * HID, HID, tid);     \
    if (tid < 32) cpa16(b_ + 32768 + tid * 16, amask + b * S_LEN + (sblk) * 128 + tid * 4); \
    CP_COMMIT();                                                                  \
  } while (0)

    // Q tile (once) + first ring
    load_stage<128>(sb + 0,    gQ,      HID, tid);
    load_stage<128>(sb + 8192, gQ + 32, HID, tid);
    PVF_LOAD(0, 0);

    float accO[8][4] = {};
    float rsL = 0.f, rsH = 0.f;
    const int arow = w * 16 + l7 + l8 * 8;

    for (int sblk = 0; sblk < 32; sblk++) {
        if (sblk + 1 < 32) { PVF_LOAD((sblk + 1) & 1, sblk + 1); CP_WAIT(1); }
        else { CP_WAIT(0); }
        __syncthreads();
        const uint32_t rb = sb + 16384 + (sblk & 1) * 33280;
        const int* mask_s = (const int*)(sm + 16384 + (sblk & 1) * 33280 + 32768);

        #pragma unroll
        for (int half = 0; half < 2; half++) {
            // --- S = Q.K^T for s-cols [64*half, 64*half+64) ---
            float sacc[8][4] = {};
            #pragma unroll
            for (int chunk = 0; chunk < 2; chunk++) {
                const uint32_t qb = sb + chunk * 8192;
                const uint32_t kb = rb + chunk * 8192;
                #pragma unroll
                for (int ks = 0; ks < 2; ks++) {
                    uint32_t ah[4];
                    ldsm4(ah, qb + swzoff(arow, ks * 2 + l16));
                    uint32_t bhf[4][4];
                    #pragma unroll
                    for (int p = 0; p < 4; p++)
                        ldsm4(bhf[p], kb + swzoff(half * 64 + l16 * 8 + l7 + p * 16,
                                                  ks * 2 + l8));
                    #pragma unroll
                    for (int nj = 0; nj < 8; nj++)
                        mma_f16(sacc[nj], ah, &bhf[nj >> 1][(nj & 1) * 2]);
                }
            }
            // --- exp + mask + rowsum + pack P frags ---
            uint32_t pa[4][4];
            #pragma unroll
            for (int nt = 0; nt < 8; nt++) {
                const int sc = half * 64 + nt * 8 + (lane & 3) * 2;
                const int m0 = mask_s[sc], m1 = mask_s[sc + 1];
                const float e0 = m0 ? __expf(sacc[nt][0] - 4.f) : 0.f;
                const float e1 = m1 ? __expf(sacc[nt][1] - 4.f) : 0.f;
                const float e2 = m0 ? __expf(sacc[nt][2] - 4.f) : 0.f;
                const float e3 = m1 ? __expf(sacc[nt][3] - 4.f) : 0.f;
                rsL += e0 + e1;
                rsH += e2 + e3;
                pa[nt >> 1][(nt & 1) * 2 + 0] = packh2(e0, e1);
                pa[nt >> 1][(nt & 1) * 2 + 1] = packh2(e2, e3);
            }
            // --- P.V accumulate (k = 64 s of this half) ---
            #pragma unroll
            for (int j = 0; j < 4; j++) {
                const int r = half * 64 + j * 16 + (g & 1) * 8 + q;
                #pragma unroll
                for (int hh = 0; hh < 4; hh++) {
                    const int cb = hh * 2 + (g >> 1);
                    uint32_t b4[4];
                    ldsm4t(b4, rb + 16384 + (uint32_t)(r * 128 + (((cb ^ r) & 7) << 4)));
                    mma_f16(accO[hh * 2 + 0], pa[j], &b4[0]);
                    mma_f16(accO[hh * 2 + 1], pa[j], &b4[2]);
                }
            }
        }
        __syncthreads();
    }
#undef PVF_LOAD

    // reduce row sums across the 4 lanes sharing a row
    rsL += __shfl_xor_sync(0xFFFFFFFFu, rsL, 1);
    rsL += __shfl_xor_sync(0xFFFFFFFFu, rsL, 2);
    rsH += __shfl_xor_sync(0xFFFFFFFFu, rsH, 1);
    rsH += __shfl_xor_sync(0xFFFFFFFFu, rsH, 2);
    const float invL = 1.0f / rsL, invH = 1.0f / rsH;

    const int row = lane >> 2;
    const int tA = t0 + w * 16 + row;
    const size_t moA = (size_t)(b * T_LEN + tA) * HID + h * HD;
    const size_t moB = moA + 8 * HID;
    #pragma unroll
    for (int nt = 0; nt < 8; nt++) {
        const int n = nt * 8 + (lane & 3) * 2;
        *(__half2*)(attH + moA + n) =
            __halves2half2(__float2half_rn(accO[nt][0] * invL),
                           __float2half_rn(accO[nt][1] * invL));
        *(__half2*)(attH + moB + n) =
            __halves2half2(__float2half_rn(accO[nt][2] * invH),
                           __float2half_rn(accO[nt][3] * invH));
    }
}

// ---------------------------------------------------------------------------
extern "C" void kernel_launch(void* const* d_in, const int* in_sizes, int n_in,
                              void* d_out, int out_size) {
    const float* query  = (const float*)d_in[0];
    const float* key    = (const float*)d_in[1];
    const float* value  = (const float*)d_in[2];
    const int*   amask  = (const int*)d_in[3];
    const int*   segids = (const int*)d_in[4];
    const float* Wq = (const float*)d_in[5];
    const float* bq = (const float*)d_in[6];
    const float* Wk = (const float*)d_in[7];
    const float* bk = (const float*)d_in[8];
    const float* Wv = (const float*)d_in[9];
    const float* bv = (const float*)d_in[10];
    const float* Wo = (const float*)d_in[11];
    const float* bo = (const float*)d_in[12];
    const float* seg_emb = (const float*)d_in[13];
    float* out = (float*)d_out;

    __half *qh, *kh, *vh;
    __half *wqh, *wql, *wkh, *wkl, *wvh, *woh;
    __half *Qh, *Kh, *Vh, *ah;
    float *ps, *rs;
    cudaGetSymbolAddress((void**)&qh, g_qh);
    cudaGetSymbolAddress((void**)&kh, g_kh);
    cudaGetSymbolAddress((void**)&vh, g_vh);
    cudaGetSymbolAddress((void**)&wqh, g_wqh); cudaGetSymbolAddress((void**)&wql, g_wql);
    cudaGetSymbolAddress((void**)&wkh, g_wkh); cudaGetSymbolAddress((void**)&wkl, g_wkl);
    cudaGetSymbolAddress((void**)&wvh, g_wvh);
    cudaGetSymbolAddress((void**)&woh, g_woh);
    cudaGetSymbolAddress((void**)&Qh, g_Qh);
    cudaGetSymbolAddress((void**)&Kh, g_Kh);
    cudaGetSymbolAddress((void**)&Vh, g_Vh);
    cudaGetSymbolAddress((void**)&ps, g_ps);
    cudaGetSymbolAddress((void**)&rs, g_rs);
    cudaGetSymbolAddress((void**)&ah, g_ah);

    cudaFuncSetAttribute(proj2<0>, cudaFuncAttributeMaxDynamicSharedMemorySize, 73728);
    cudaFuncSetAttribute(proj2<1>, cudaFuncAttributeMaxDynamicSharedMemorySize, 73728);
    cudaFuncSetAttribute(proj1<0>, cudaFuncAttributeMaxDynamicSharedMemorySize, 49152);
    cudaFuncSetAttribute(proj1<1>, cudaFuncAttributeMaxDynamicSharedMemorySize, 49152);
    cudaFuncSetAttribute(rowsum_pass, cudaFuncAttributeMaxDynamicSharedMemorySize, 32768);
    cudaFuncSetAttribute(prov_fused, cudaFuncAttributeMaxDynamicSharedMemorySize, 67072);
    cudaFuncSetAttribute(pv_fused, cudaFuncAttributeMaxDynamicSharedMemorySize, 82944);

    // input + weight conversions
    conv_h<<<4096, 256>>>(query, qh);
    conv_h<<<32768, 256>>>(key, kh);
    conv_h<<<32768, 256>>>(value, vh);
    dim3 wtb(32, 8), wtg(32, 32);
    conv_wT<<<wtg, wtb>>>(Wq, wqh, wql);
    conv_wT<<<wtg, wtb>>>(Wk, wkh, wkl);
    conv_wT<<<wtg, wtb>>>(Wv, wvh, nullptr);
    conv_wT<<<wtg, wtb>>>(Wo, woh, nullptr);

    // projections
    proj2<0><<<dim3(8, 16),  256, 73728>>>(qh, wqh, wql, bq, nullptr, nullptr, Qh);
    proj2<1><<<dim3(8, 128), 256, 73728>>>(kh, wkh, wkl, bk, segids, seg_emb, Kh);
    proj1<0><<<dim3(8, 128), 256, 49152>>>(vh, wvh, bv, nullptr, Vh);

    // attention: rowsums (for provenance), fused PV (online rowsum), fused provenance
    rowsum_pass<<<dim3(32, 4, NBH), 256, 32768>>>(Qh, Kh, amask, ps);
    rowsum_reduce<<<128, 256>>>(ps, rs);
    pv_fused<<<dim3(4, 64), 256, 82944>>>(Qh, Kh, Vh, amask, ah);
    prov_fused<<<dim3(32, 4, 4), 256, 67072>>>(Qh, Kh, rs, amask, out + (size_t)2048 * HID);

    // output projection -> d_out
    proj1<1><<<dim3(8, 16), 256, 49152>>>(ah, woh, bo, out, nullptr);
}

// round 15
// speedup vs baseline: 1.3038x; 1.3038x over previous
#include <cuda_runtime.h>
#include <cuda_fp16.h>
#include <cstdint>
#include <cstddef>

#define B_SZ   4
#define T_LEN  512
#define S_LEN  4096
#define HID    1024
#define NH     16
#define HD     64
#define NBH    (B_SZ * NH)

// ---------------------------------------------------------------------------
// helpers
// ---------------------------------------------------------------------------
__device__ __forceinline__ uint32_t smem_u32(const void* p) {
    uint32_t a;
    asm("{ .reg .u64 t; cvta.to.shared.u64 t, %1; cvt.u32.u64 %0, t; }" : "=r"(a) : "l"(p));
    return a;
}
// 64B-row tile swizzle (K-major tiles)
__device__ __forceinline__ uint32_t swzoff(int row, int chunk) {
    const int v = (row & 3) ^ ((row >> 2) & 1);
    return (uint32_t)(row * 64 + (((chunk ^ v) & 3) << 4));
}
__device__ __forceinline__ void cpa16(uint32_t dst, const void* src) {
    asm volatile("cp.async.cg.shared.global [%0], [%1], 16;" :: "r"(dst), "l"(src));
}
#define CP_COMMIT() asm volatile("cp.async.commit_group;" ::: "memory")
#define CP_WAIT(n)  asm volatile("cp.async.wait_group %0;" :: "n"(n) : "memory")

__device__ __forceinline__ void ldsm4(uint32_t* r, uint32_t a) {
    asm volatile("ldmatrix.sync.aligned.m8n8.x4.shared.b16 {%0,%1,%2,%3}, [%4];"
                 : "=r"(r[0]), "=r"(r[1]), "=r"(r[2]), "=r"(r[3]) : "r"(a));
}
__device__ __forceinline__ void ldsm4t(uint32_t* r, uint32_t a) {
    asm volatile("ldmatrix.sync.aligned.m8n8.x4.trans.shared.b16 {%0,%1,%2,%3}, [%4];"
                 : "=r"(r[0]), "=r"(r[1]), "=r"(r[2]), "=r"(r[3]) : "r"(a));
}
__device__ __forceinline__ void mma_f16(float* d, const uint32_t* a, const uint32_t* b) {
    asm volatile("mma.sync.aligned.m16n8k16.row.col.f32.f16.f16.f32 "
                 "{%0,%1,%2,%3}, {%4,%5,%6,%7}, {%8,%9}, {%0,%1,%2,%3};"
                 : "+f"(d[0]), "+f"(d[1]), "+f"(d[2]), "+f"(d[3])
                 : "r"(a[0]), "r"(a[1]), "r"(a[2]), "r"(a[3]), "r"(b[0]), "r"(b[1]));
}
__device__ __forceinline__ void split2h(float v, __half& h, __half& l) {
    h = __float2half_rn(v);
    l = __float2half_rn(v - __half2float(h));
}

// Load a [ROWS x 32] fp16 tile (row stride = stride elems) into swizzled SMEM
template<int ROWS>
__device__ __forceinline__ void load_stage(uint32_t sbuf, const __half* g,
                                           int stride, int tid) {
    #pragma unroll
    for (int i = tid; i < ROWS * 4; i += 256) {
        const int row = i >> 2, ch = i & 3;
        cpa16(sbuf + swzoff(row, ch), g + (size_t)row * stride + ch * 8);
    }
}
// Load a [32 x 64] fp16 tile (128B rows, chunk-XOR swizzle) for trans-B (V)
__device__ __forceinline__ void load_vtile(uint32_t sbuf, const __half* g,
                                           int stride, int tid) {
    if (tid < 256) {
        const int row = tid >> 3, ch = tid & 7;
        cpa16(sbuf + (uint32_t)(row * 128 + (((ch ^ row) & 7) << 4)),
              g + (size_t)row * stride + ch * 8);
    }
}

// One 32-k stage, A single + B hi/lo, 2 products (Q projection).
__device__ __forceinline__ void stage_compute2(uint32_t sA,
                                               uint32_t sBh, uint32_t sBl,
                                               int wmr, int wnr, int lane,
                                               float (*acc)[4][4]) {
    const int l7 = lane & 7, l8 = (lane >> 3) & 1, l16 = (lane >> 4) & 1;
    const int arow = wmr + l7 + l8 * 8;
    const int brow = wnr + l16 * 8 + l7;
    #pragma unroll
    for (int ks = 0; ks < 2; ks++) {
        uint32_t ah[4][4], bh[2][4], bl[2][4];
        #pragma unroll
        for (int mi = 0; mi < 4; mi++)
            ldsm4(ah[mi], sA + swzoff(arow + mi * 16, ks * 2 + l16));
        #pragma unroll
        for (int p = 0; p < 2; p++) {
            const uint32_t off = swzoff(brow + p * 16, ks * 2 + l8);
            ldsm4(bh[p], sBh + off);
            ldsm4(bl[p], sBl + off);
        }
        #pragma unroll
        for (int mi = 0; mi < 4; mi++)
            #pragma unroll
            for (int nj = 0; nj < 4; nj++) {
                mma_f16(acc[mi][nj], ah[mi], &bh[nj >> 1][(nj & 1) * 2]);
                mma_f16(acc[mi][nj], ah[mi], &bl[nj >> 1][(nj & 1) * 2]);
            }
    }
}

// One 32-k stage, A single + B single, 1 product (K/V/O projections, scores).
__device__ __forceinline__ void stage_compute1(uint32_t sA, uint32_t sB,
                                               int wmr, int wnr, int lane,
                                               float (*acc)[4][4]) {
    const int l7 = lane & 7, l8 = (lane >> 3) & 1, l16 = (lane >> 4) & 1;
    const int arow = wmr + l7 + l8 * 8;
    const int brow = wnr + l16 * 8 + l7;
    #pragma unroll
    for (int ks = 0; ks < 2; ks++) {
        uint32_t ah[4][4], bh[2][4];
        #pragma unroll
        for (int mi = 0; mi < 4; mi++)
            ldsm4(ah[mi], sA + swzoff(arow + mi * 16, ks * 2 + l16));
        #pragma unroll
        for (int p = 0; p < 2; p++)
            ldsm4(bh[p], sB + swzoff(brow + p * 16, ks * 2 + l8));
        #pragma unroll
        for (int mi = 0; mi < 4; mi++)
            #pragma unroll
            for (int nj = 0; nj < 4; nj++)
                mma_f16(acc[mi][nj], ah[mi], &bh[nj >> 1][(nj & 1) * 2]);
    }
}

// One 32-k PV stage: A = E single (K-major, MI m-frags), B = V via ldmatrix.trans
template<int MI>
__device__ __forceinline__ void pv_stage1(uint32_t sA, uint32_t sB,
                                          int wmr, int wnr, int lane,
                                          float (*acc)[4][4]) {
    const int l7 = lane & 7, l8 = (lane >> 3) & 1, l16 = (lane >> 4) & 1;
    const int arow = wmr + l7 + l8 * 8;
    const int g = lane >> 3, q = lane & 7;
    #pragma unroll
    for (int ks = 0; ks < 2; ks++) {
        uint32_t ah[MI][4];
        #pragma unroll
        for (int mi = 0; mi < MI; mi++)
            ldsm4(ah[mi], sA + swzoff(arow + mi * 16, ks * 2 + l16));
        #pragma unroll
        for (int half = 0; half < 2; half++) {
            const int r = ks * 16 + (g & 1) * 8 + q;
            const int cb = ((wnr + half * 16) >> 3) + (g >> 1);
            const uint32_t off = (uint32_t)(r * 128 + (((cb ^ r) & 7) << 4));
            uint32_t bh4[4];
            ldsm4t(bh4, sB + off);
            #pragma unroll
            for (int mi = 0; mi < MI; mi++)
                #pragma unroll
                for (int u = 0; u < 2; u++)
                    mma_f16(acc[mi][half * 2 + u], ah[mi], &bh4[u * 2]);
        }
    }
}

// ---------------- scratch ----------------
__device__ __half g_qh[2048 * HID];
__device__ __half g_kh[16384 * HID];
__device__ __half g_vh[16384 * HID];
__device__ __half g_wqh[HID * HID], g_wql[HID * HID];
__device__ __half g_wkh[HID * HID];
__device__ __half g_wvh[HID * HID];
__device__ __half g_woh[HID * HID];
__device__ __half g_Qh[2048 * HID];
__device__ __half g_Kh[16384 * HID];
__device__ __half g_Vh[16384 * HID];
__device__ __half g_E[(size_t)NBH * T_LEN * S_LEN];     // exp(score-4), fp16
__device__ float  g_ps[(size_t)NBH * T_LEN * 32];       // per-block partial row sums
__device__ float  g_rs[NBH * T_LEN];                    // row sums
__device__ __half g_ah[2048 * HID];

// ---------------- conversions ----------------
__global__ __launch_bounds__(256)
void conv_h(const float* __restrict__ X, __half* __restrict__ H) {
    const size_t u = (size_t)blockIdx.x * 256 + threadIdx.x;
    float2 v = reinterpret_cast<const float2*>(X)[u];
    reinterpret_cast<__half2*>(H)[u] =
        __halves2half2(__float2half_rn(v.x), __float2half_rn(v.y));
}
__global__ __launch_bounds__(256)
void conv_wT(const float* __restrict__ W, __half* __restrict__ WTh,
             __half* __restrict__ WTl) {
    __shared__ float t[32][33];
    const int k0 = blockIdx.x * 32, n0 = blockIdx.y * 32;
    const int tx = threadIdx.x, ty = threadIdx.y;
    for (int r = ty; r < 32; r += 8) t[r][tx] = W[(size_t)(k0 + r) * HID + n0 + tx];
    __syncthreads();
    for (int r = ty; r < 32; r += 8) {
        __half h, l;
        split2h(t[tx][r], h, l);
        WTh[(size_t)(n0 + r) * HID + k0 + tx] = h;
        if (WTl) WTl[(size_t)(n0 + r) * HID + k0 + tx] = l;
    }
}

// ---------------- Q projection (2-product weights, single fp16 out, *0.125) ----------------
__global__ __launch_bounds__(256)
void proj2q(const __half* __restrict__ A,
            const __half* __restrict__ Bh, const __half* __restrict__ Bl,
            const float* __restrict__ bias, __half* __restrict__ outH) {
    extern __shared__ __align__(128) char sm[];
    const uint32_t sb = smem_u32(sm);
    const int tid = threadIdx.x, lane = tid & 31, w = tid >> 5;
    const int wmr = (w & 1) * 64, wnr = (w >> 1) * 32;
    const int n0 = blockIdx.x * 128, m0 = blockIdx.y * 128;
    const __half* gA  = A + (size_t)m0 * HID;
    const __half* gBh = Bh + (size_t)n0 * HID;
    const __half* gBl = Bl + (size_t)n0 * HID;

#define PJ_LOAD(st, ko) do {                                \
    const uint32_t b_ = sb + ((st) % 3) * 24576;            \
    load_stage<128>(b_ + 0,     gA  + (ko), HID, tid);      \
    load_stage<128>(b_ + 8192,  gBh + (ko), HID, tid);      \
    load_stage<128>(b_ + 16384, gBl + (ko), HID, tid);      \
    CP_COMMIT();                                            \
  } while (0)

    float acc[4][4][4] = {};
    PJ_LOAD(0, 0);
    PJ_LOAD(1, 32);
    const int NST = HID / 32;
    for (int s = 0; s < NST; s++) {
        if (s + 2 < NST) { PJ_LOAD(s + 2, (s + 2) * 32); CP_WAIT(2); }
        else if (s + 1 < NST) { CP_WAIT(1); }
        else { CP_WAIT(0); }
        __syncthreads();
        const uint32_t cur = sb + (s % 3) * 24576;
        stage_compute2(cur, cur + 8192, cur + 16384, wmr, wnr, lane, acc);
        __syncthreads();
    }
#undef PJ_LOAD

    const int mq = lane >> 2, nq = (lane & 3) * 2;
    #pragma unroll
    for (int mi = 0; mi < 4; mi++)
        #pragma unroll
        for (int half = 0; half < 2; half++) {
            const int m = m0 + wmr + mi * 16 + mq + half * 8;
            #pragma unroll
            for (int nj = 0; nj < 4; nj++) {
                const int n = n0 + wnr + nj * 8 + nq;
                float v0 = (acc[mi][nj][half * 2 + 0] + bias[n]) * 0.125f;
                float v1 = (acc[mi][nj][half * 2 + 1] + bias[n + 1]) * 0.125f;
                *(__half2*)(outH + (size_t)m * HID + n) =
                    __halves2half2(__float2half_rn(v0), __float2half_rn(v1));
            }
        }
}

// ---------------- K/V/O projection (1-product) ----------------
// MODE 0: V (bias, fp16 out)  1: O (bias, fp32 out)  2: K (bias+seg, fp16 out)
template<int MODE>
__global__ __launch_bounds__(256)
void proj1(const __half* __restrict__ A, const __half* __restrict__ B,
           const float* __restrict__ bias, const int* __restrict__ segids,
           const float* __restrict__ seg_emb, float* __restrict__ outF,
           __half* __restrict__ outH) {
    extern __shared__ __align__(128) char sm[];
    const uint32_t sb = smem_u32(sm);
    const int tid = threadIdx.x, lane = tid & 31, w = tid >> 5;
    const int wmr = (w & 1) * 64, wnr = (w >> 1) * 32;
    const int n0 = blockIdx.x * 128, m0 = blockIdx.y * 128;
    const __half* gA = A + (size_t)m0 * HID;
    const __half* gB = B + (size_t)n0 * HID;

#define P1_LOAD(st, ko) do {                                \
    const uint32_t b_ = sb + ((st) % 3) * 16384;            \
    load_stage<128>(b_ + 0,    gA + (ko), HID, tid);        \
    load_stage<128>(b_ + 8192, gB + (ko), HID, tid);        \
    CP_COMMIT();                                            \
  } while (0)

    float acc[4][4][4] = {};
    P1_LOAD(0, 0);
    P1_LOAD(1, 32);
    const int NST = HID / 32;
    for (int s = 0; s < NST; s++) {
        if (s + 2 < NST) { P1_LOAD(s + 2, (s + 2) * 32); CP_WAIT(2); }
        else if (s + 1 < NST) { CP_WAIT(1); }
        else { CP_WAIT(0); }
        __syncthreads();
        const uint32_t cur = sb + (s % 3) * 16384;
        stage_compute1(cur, cur + 8192, wmr, wnr, lane, acc);
        __syncthreads();
    }
#undef P1_LOAD

    const int mq = lane >> 2, nq = (lane & 3) * 2;
    #pragma unroll
    for (int mi = 0; mi < 4; mi++)
        #pragma unroll
        for (int half = 0; half < 2; half++) {
            const int m = m0 + wmr + mi * 16 + mq + half * 8;
            const int sid = (MODE == 2) ? segids[m] : 0;
            #pragma unroll
            for (int nj = 0; nj < 4; nj++) {
                const int n = n0 + wnr + nj * 8 + nq;
                float v0 = acc[mi][nj][half * 2 + 0] + bias[n];
                float v1 = acc[mi][nj][half * 2 + 1] + bias[n + 1];
                if (MODE == 2) {
                    v0 += seg_emb[(size_t)sid * HID + n];
                    v1 += seg_emb[(size_t)sid * HID + n + 1];
                }
                if (MODE != 1) {
                    *(__half2*)(outH + (size_t)m * HID + n) =
                        __halves2half2(__float2half_rn(v0), __float2half_rn(v1));
                } else {
                    *(float2*)(outF + (size_t)m * HID + n) = make_float2(v0, v1);
                }
            }
        }
}

// ---------------- scores+exp: E[bh,t,s] = exp(Q·K^T - 4), partial row sums ----------------
__global__ __launch_bounds__(256)
void scores_exp(const __half* __restrict__ Qh, const __half* __restrict__ Kh,
                const int* __restrict__ amask, __half* __restrict__ E,
                float* __restrict__ gps) {
    extern __shared__ __align__(128) char sm[];
    __shared__ float psum[128][4];
    const uint32_t sb = smem_u32(sm);
    const int tid = threadIdx.x, lane = tid & 31, w = tid >> 5;
    const int wmr = (w & 1) * 64, wnr = (w >> 1) * 32;
    const int bh = blockIdx.z, b = bh >> 4, h = bh & 15;
    const int t0 = blockIdx.y * 128, s0 = blockIdx.x * 128;
    const __half* gA = Qh + (size_t)(b * T_LEN + t0) * HID + h * HD;
    const __half* gB = Kh + (size_t)(b * S_LEN + s0) * HID + h * HD;

    float acc[4][4][4] = {};
    load_stage<128>(sb + 0,    gA, HID, tid);
    load_stage<128>(sb + 8192, gB, HID, tid);
    CP_COMMIT();
    load_stage<128>(sb + 16384, gA + 32, HID, tid);
    load_stage<128>(sb + 24576, gB + 32, HID, tid);
    CP_COMMIT();
    for (int s = 0; s < 2; s++) {
        if (s == 0) CP_WAIT(1);
        else CP_WAIT(0);
        __syncthreads();
        const uint32_t cur = sb + s * 16384;
        stage_compute1(cur, cur + 8192, wmr, wnr, lane, acc);
        __syncthreads();
    }

    const int mq = lane >> 2, nq = (lane & 3) * 2;
    __half* dstB = E + (size_t)bh * T_LEN * S_LEN;
    #pragma unroll
    for (int mi = 0; mi < 4; mi++)
        #pragma unroll
        for (int half = 0; half < 2; half++) {
            const int t = t0 + wmr + mi * 16 + mq + half * 8;
            float rsum = 0.f;
            #pragma unroll
            for (int nj = 0; nj < 4; nj++) {
                const int sidx = s0 + wnr + nj * 8 + nq;
                float e0 = (amask[b * S_LEN + sidx] == 0) ? 0.f
                           : __expf(acc[mi][nj][half * 2 + 0] - 4.f);
                float e1 = (amask[b * S_LEN + sidx + 1] == 0) ? 0.f
                           : __expf(acc[mi][nj][half * 2 + 1] - 4.f);
                rsum += e0 + e1;
                __half2 h2;
                h2.x = __float2half_rn(e0);
                h2.y = __float2half_rn(e1);
                *(__half2*)(dstB + (size_t)t * S_LEN + sidx) = h2;
            }
            rsum += __shfl_xor_sync(0xFFFFFFFFu, rsum, 1);
            rsum += __shfl_xor_sync(0xFFFFFFFFu, rsum, 2);
            if ((lane & 3) == 0)
                psum[wmr + mi * 16 + half * 8 + mq][w >> 1] = rsum;
        }
    __syncthreads();
    if (tid < 128) {
        const float tot = psum[tid][0] + psum[tid][1] + psum[tid][2] + psum[tid][3];
        gps[((size_t)bh * T_LEN + t0 + tid) * 32 + blockIdx.x] = tot;
    }
}

// ---------------- row-sum reduce: rs[r] = sum of 32 partials ----------------
__global__ __launch_bounds__(256)
void rowsum_reduce(const float* __restrict__ gps, float* __restrict__ rs) {
    const int r = blockIdx.x * 256 + threadIdx.x;
    const float4* p = reinterpret_cast<const float4*>(gps + (size_t)r * 32);
    float s = 0.f;
    #pragma unroll
    for (int i = 0; i < 8; i++) {
        float4 v = p[i];
        s += v.x + v.y + v.z + v.w;
    }
    rs[r] = s;
}

// ---------------- provenance = head-mean of E/rowsum ----------------
__global__ __launch_bounds__(256)
void provenance_kernel(const __half* __restrict__ E, const float* __restrict__ rs,
                       float* __restrict__ out) {
    const size_t u = (size_t)blockIdx.x * 256 + threadIdx.x;
    const int s2 = (int)(u & 2047);
    const int t  = (int)((u >> 11) & 511);
    const int b  = (int)(u >> 20);
    float s0 = 0.f, s1 = 0.f;
    #pragma unroll
    for (int h = 0; h < NH; h++) {
        const int bh = b * NH + h;
        const float inv = 1.0f / rs[bh * T_LEN + t];
        const size_t o = (((size_t)bh * T_LEN + t) * S_LEN) / 2 + s2;
        __half2 h2 = reinterpret_cast<const __half2*>(E)[o];
        s0 += __half2float(h2.x) * inv;
        s1 += __half2float(h2.y) * inv;
    }
    reinterpret_cast<float2*>(out)[u] = make_float2(s0 * (1.0f / NH), s1 * (1.0f / NH));
}

// ---------------- P·V: C[128,64] per CTA, K=4096, normalized epilogue ----------------
__global__ __launch_bounds__(256)
void pv_gemm(const __half* __restrict__ E, const __half* __restrict__ Vh,
             const float* __restrict__ rs, __half* __restrict__ attH) {
    extern __shared__ __align__(128) char sm[];
    const uint32_t sb = smem_u32(sm);
    const int tid = threadIdx.x, lane = tid & 31, w = tid >> 5;
    const int wmr = (w & 3) * 32, wnr = (w >> 2) * 32;
    const int bh = blockIdx.y, b = bh >> 4, h = bh & 15;
    const int t0 = blockIdx.x * 128;
    const __half* gA = E + ((size_t)bh * T_LEN + t0) * S_LEN;
    const __half* gB = Vh + (size_t)(b * S_LEN) * HID + h * HD;

#define PV_LOAD(st, ko) do {                                              \
    const uint32_t b_ = sb + ((st) % 3) * 12288;                          \
    load_stage<128>(b_ + 0, gA + (ko), S_LEN, tid);                       \
    load_vtile(b_ + 8192, gB + (size_t)(ko) * HID, HID, tid);             \
    CP_COMMIT();                                                          \
  } while (0)

    float acc[2][4][4] = {};
    PV_LOAD(0, 0);
    PV_LOAD(1, 32);
    const int NST = S_LEN / 32;
    for (int s = 0; s < NST; s++) {
        if (s + 2 < NST) { PV_LOAD(s + 2, (s + 2) * 32); CP_WAIT(2); }
        else if (s + 1 < NST) { CP_WAIT(1); }
        else { CP_WAIT(0); }
        __syncthreads();
        const uint32_t cur = sb + (s % 3) * 12288;
        pv_stage1<2>(cur, cur + 8192, wmr, wnr, lane, acc);
        __syncthreads();
    }
#undef PV_LOAD

    const int mq = lane >> 2, nq = (lane & 3) * 2;
    #pragma unroll
    for (int mi = 0; mi < 2; mi++)
        #pragma unroll
        for (int half = 0; half < 2; half++) {
            const int t = t0 + wmr + mi * 16 + mq + half * 8;
            const float inv = 1.0f / rs[bh * T_LEN + t];
            const size_t mo = (size_t)(b * T_LEN + t) * HID + h * HD;
            #pragma unroll
            for (int nj = 0; nj < 4; nj++) {
                const int n = wnr + nj * 8 + nq;
                __half2 h2;
                h2.x = __float2half_rn(acc[mi][nj][half * 2 + 0] * inv);
                h2.y = __float2half_rn(acc[mi][nj][half * 2 + 1] * inv);
                *(__half2*)(attH + mo + n) = h2;
            }
        }
}

// ---------------------------------------------------------------------------
extern "C" void kernel_launch(void* const* d_in, const int* in_sizes, int n_in,
                              void* d_out, int out_size) {
    const float* query  = (const float*)d_in[0];
    const float* key    = (const float*)d_in[1];
    const float* value  = (const float*)d_in[2];
    const int*   amask  = (const int*)d_in[3];
    const int*   segids = (const int*)d_in[4];
    const float* Wq = (const float*)d_in[5];
    const float* bq = (const float*)d_in[6];
    const float* Wk = (const float*)d_in[7];
    const float* bk = (const float*)d_in[8];
    const float* Wv = (const float*)d_in[9];
    const float* bv = (const float*)d_in[10];
    const float* Wo = (const float*)d_in[11];
    const float* bo = (const float*)d_in[12];
    const float* seg_emb = (const float*)d_in[13];
    float* out = (float*)d_out;

    __half *qh, *kh, *vh;
    __half *wqh, *wql, *wkh, *wvh, *woh;
    __half *Qh, *Kh, *Vh, *E, *ah;
    float *ps, *rs;
    cudaGetSymbolAddress((void**)&qh, g_qh);
    cudaGetSymbolAddress((void**)&kh, g_kh);
    cudaGetSymbolAddress((void**)&vh, g_vh);
    cudaGetSymbolAddress((void**)&wqh, g_wqh); cudaGetSymbolAddress((void**)&wql, g_wql);
    cudaGetSymbolAddress((void**)&wkh, g_wkh);
    cudaGetSymbolAddress((void**)&wvh, g_wvh);
    cudaGetSymbolAddress((void**)&woh, g_woh);
    cudaGetSymbolAddress((void**)&Qh, g_Qh);
    cudaGetSymbolAddress((void**)&Kh, g_Kh);
    cudaGetSymbolAddress((void**)&Vh, g_Vh);
    cudaGetSymbolAddress((void**)&E, g_E);
    cudaGetSymbolAddress((void**)&ps, g_ps);
    cudaGetSymbolAddress((void**)&rs, g_rs);
    cudaGetSymbolAddress((void**)&ah, g_ah);

    cudaFuncSetAttribute(proj2q, cudaFuncAttributeMaxDynamicSharedMemorySize, 73728);
    cudaFuncSetAttribute(proj1<0>, cudaFuncAttributeMaxDynamicSharedMemorySize, 49152);
    cudaFuncSetAttribute(proj1<1>, cudaFuncAttributeMaxDynamicSharedMemorySize, 49152);
    cudaFuncSetAttribute(proj1<2>, cudaFuncAttributeMaxDynamicSharedMemorySize, 49152);
    cudaFuncSetAttribute(scores_exp, cudaFuncAttributeMaxDynamicSharedMemorySize, 32768);
    cudaFuncSetAttribute(pv_gemm, cudaFuncAttributeMaxDynamicSharedMemorySize, 36864);

    // input + weight conversions
    conv_h<<<4096, 256>>>(query, qh);
    conv_h<<<32768, 256>>>(key, kh);
    conv_h<<<32768, 256>>>(value, vh);
    dim3 wtb(32, 8), wtg(32, 32);
    conv_wT<<<wtg, wtb>>>(Wq, wqh, wql);
    conv_wT<<<wtg, wtb>>>(Wk, wkh, nullptr);
    conv_wT<<<wtg, wtb>>>(Wv, wvh, nullptr);
    conv_wT<<<wtg, wtb>>>(Wo, woh, nullptr);

    // projections
    proj2q<<<dim3(8, 16), 256, 73728>>>(qh, wqh, wql, bq, Qh);
    proj1<2><<<dim3(8, 128), 256, 49152>>>(kh, wkh, bk, segids, seg_emb, nullptr, Kh);
    proj1<0><<<dim3(8, 128), 256, 49152>>>(vh, wvh, bv, nullptr, nullptr, nullptr, Vh);

    // fused scores+exp (single launch), deterministic row-sum reduction
    scores_exp<<<dim3(32, 4, NBH), 256, 32768>>>(Qh, Kh, amask, E, ps);
    rowsum_reduce<<<NBH * T_LEN / 256, 256>>>(ps, rs);

    // provenance + attended
    provenance_kernel<<<16384, 256>>>(E, rs, out + (size_t)2048 * HID);
    pv_gemm<<<dim3(4, 64), 256, 36864>>>(E, Vh, rs, ah);

    // output projection -> d_out
    proj1<1><<<dim3(8, 16), 256, 49152>>>(ah, woh, bo, nullptr, nullptr, out, nullptr);
}